// round 5
// baseline (speedup 1.0000x reference)
#include <cuda_runtime.h>

#define NB 8
#define NC 64
#define NN 2304     // 48*48
#define NPROJ 160   // 16 + 16 + 64 + 64 projection rows

// Scratch (device globals: allocation-free rule)
__device__ float g_qk[2][NB][16][NN];   // [attn][b][row 0-7=q, 8-15=k][n]
__device__ float g_v[2][NB][NC][NN];    // g_v[0]=v1, g_v[1]=v2
__device__ float g_rinv[2][NB][NN];     // 1/Z per attn row

// ---------------------------------------------------------------------------
// Kernel 1: all four 1x1-conv projections fused.
// Block: 64 columns of n, all 160 output rows. smem: x1/x2 tiles + all weights.
// ---------------------------------------------------------------------------
__global__ __launch_bounds__(256) void k_proj(
    const float* __restrict__ x1, const float* __restrict__ x2,
    const float* __restrict__ Wqk1, const float* __restrict__ bqk1,
    const float* __restrict__ Wqk2, const float* __restrict__ bqk2,
    const float* __restrict__ Wv1,  const float* __restrict__ bv1,
    const float* __restrict__ Wv2,  const float* __restrict__ bv2)
{
    extern __shared__ float sm[];
    float* xs1 = sm;             // [64][64]
    float* xs2 = sm + 4096;      // [64][64]
    float* ws  = sm + 8192;      // [160][64]
    float* bs  = sm + 18432;     // [160]
    const int b   = blockIdx.y;
    const int n0  = blockIdx.x * 64;
    const int tid = threadIdx.x;

    for (int idx = tid; idx < NPROJ * 64; idx += 256) {
        int r = idx >> 6, c = idx & 63;
        float w;
        if (r < 16)      w = Wqk1[r * 64 + c];
        else if (r < 32) w = Wqk2[(r - 16) * 64 + c];
        else if (r < 96) w = Wv1[(r - 32) * 64 + c];
        else             w = Wv2[(r - 96) * 64 + c];
        ws[idx] = w;
    }
    if (tid < NPROJ) {
        float bb;
        if (tid < 16)      bb = bqk1[tid];
        else if (tid < 32) bb = bqk2[tid - 16];
        else if (tid < 96) bb = bv1[tid - 32];
        else               bb = bv2[tid - 96];
        bs[tid] = bb;
    }
    for (int idx = tid; idx < 4096; idx += 256) {
        int c = idx >> 6, col = idx & 63;
        long gi = ((long)b * NC + c) * NN + n0 + col;
        xs1[idx] = x1[gi];
        xs2[idx] = x2[gi];
    }
    __syncthreads();

    const int rowg = tid >> 4;   // 0..15
    const int colg = tid & 15;   // 0..15 -> 4 columns each
    float acc[10][4];
    #pragma unroll
    for (int k = 0; k < 10; k++)
        #pragma unroll
        for (int j = 0; j < 4; j++) acc[k][j] = 0.f;

    for (int c = 0; c < 64; c++) {
        float4 xa = *(const float4*)&xs1[c * 64 + colg * 4];
        float4 xb = *(const float4*)&xs2[c * 64 + colg * 4];
        #pragma unroll
        for (int k = 0; k < 10; k++) {
            // k==0: qk1(x1), k==1: qk2(x2), k=2..5: v1(x1), k=6..9: v2(x2)
            const bool useb = (k == 1) || (k >= 6);
            float4 xv = useb ? xb : xa;
            float w = ws[(rowg + 16 * k) * 64 + c];
            acc[k][0] += w * xv.x;
            acc[k][1] += w * xv.y;
            acc[k][2] += w * xv.z;
            acc[k][3] += w * xv.w;
        }
    }

    #pragma unroll
    for (int k = 0; k < 10; k++) {
        int r = rowg + 16 * k;
        float bb = bs[r];
        float4 o;
        o.x = acc[k][0] + bb; o.y = acc[k][1] + bb;
        o.z = acc[k][2] + bb; o.w = acc[k][3] + bb;
        float* dst;
        if (k == 0)      dst = &g_qk[0][b][r][n0];
        else if (k == 1) dst = &g_qk[1][b][r - 16][n0];
        else if (k < 6)  dst = &g_v[0][b][r - 32][n0];
        else             dst = &g_v[1][b][r - 96][n0];
        *(float4*)&dst[colg * 4] = o;
    }
}

// ---------------------------------------------------------------------------
// Kernel 2: softmax row sums (no max-subtraction; logits are small).
// One thread per attention row i; full K tile (8 x 2304, transposed) in smem.
// ---------------------------------------------------------------------------
__global__ __launch_bounds__(256) void k_stats()
{
    extern __shared__ float ks[];   // [NN][8]
    const int a = blockIdx.y, b = blockIdx.z;
    const int i = blockIdx.x * 256 + threadIdx.x;
    const float* kb = &g_qk[a][b][8][0];
    for (int idx = threadIdx.x; idx < 8 * NN; idx += 256) {
        int c = idx / NN;
        int n = idx - c * NN;
        ks[n * 8 + c] = kb[idx];
    }
    __syncthreads();
    float q[8];
    #pragma unroll
    for (int c = 0; c < 8; c++) q[c] = g_qk[a][b][c][i];
    const float4* k4 = (const float4*)ks;
    float Z0 = 0.f, Z1 = 0.f, Z2 = 0.f, Z3 = 0.f;
    for (int j = 0; j < NN; j += 4) {
        #pragma unroll
        for (int u = 0; u < 4; u++) {
            float4 a0 = k4[(j + u) * 2];
            float4 a1 = k4[(j + u) * 2 + 1];
            float s = q[0]*a0.x + q[1]*a0.y + q[2]*a0.z + q[3]*a0.w
                    + q[4]*a1.x + q[5]*a1.y + q[6]*a1.z + q[7]*a1.w;
            float e = __expf(s);
            if (u == 0) Z0 += e; else if (u == 1) Z1 += e;
            else if (u == 2) Z2 += e; else Z3 += e;
        }
    }
    g_rinv[a][b][i] = 1.f / ((Z0 + Z1) + (Z2 + Z3));
}

// ---------------------------------------------------------------------------
// Kernel 3: O = V @ P with P recomputed on the fly (s = q.k, p = exp(s)/Z),
// then out = O*scale + x. Block = 64 (all c) x 64 j columns, sweep i tiles.
// attn index a==0 (q1k1) drives o2 = v2@attn1*beta + x2;
//            a==1 (q2k2) drives o1 = v1@attn2*gamma + x1.
// ---------------------------------------------------------------------------
__global__ __launch_bounds__(256) void k_apply(
    const float* __restrict__ x1, const float* __restrict__ x2,
    const float* __restrict__ gamma, const float* __restrict__ beta,
    float* __restrict__ out)
{
    __shared__ __align__(16) float kt[8 * 64];
    __shared__ __align__(16) float qs[8 * 64];
    __shared__ float rs[64];
    __shared__ __align__(16) float Vs[64 * 64];  // [c][il]
    __shared__ __align__(16) float ps[64 * 64];  // [il][j]
    const int a  = blockIdx.y, b = blockIdx.z;
    const int j0 = blockIdx.x * 64;
    const int tid = threadIdx.x;
    const int vsel = 1 - a;

    for (int idx = tid; idx < 512; idx += 256) {
        int c = idx >> 6, j = idx & 63;
        kt[idx] = g_qk[a][b][8 + c][j0 + j];
    }

    const int tc = tid >> 4;   // c-group: owns rows tc*4 .. tc*4+3
    const int tj = tid & 15;   // j-group: owns cols tj*4 .. tj*4+3
    float acc[4][4];
    #pragma unroll
    for (int u = 0; u < 4; u++)
        #pragma unroll
        for (int v = 0; v < 4; v++) acc[u][v] = 0.f;

    for (int it = 0; it < NN / 64; it++) {
        const int i0 = it * 64;
        __syncthreads();   // previous GEMM done before overwrite
        for (int idx = tid; idx < 4096; idx += 256) {
            int c = idx >> 6, il = idx & 63;
            Vs[idx] = g_v[vsel][b][c][i0 + il];
        }
        for (int idx = tid; idx < 512; idx += 256) {
            int c = idx >> 6, il = idx & 63;
            qs[idx] = g_qk[a][b][c][i0 + il];
        }
        if (tid < 64) rs[tid] = g_rinv[a][b][i0 + tid];
        __syncthreads();
        // p tile: 16 elements / thread
        #pragma unroll
        for (int k = 0; k < 16; k++) {
            int e = tid + k * 256;
            int il = e >> 6, j = e & 63;
            float s = 0.f;
            #pragma unroll
            for (int c = 0; c < 8; c++) s += qs[c * 64 + il] * kt[c * 64 + j];
            ps[e] = __expf(s) * rs[il];
        }
        __syncthreads();
        // 64x64 += 64x64 * 64x64, 4x4 micro-tile, float4 over i
        for (int i = 0; i < 64; i += 4) {
            float vr[4][4], pr[4][4];
            #pragma unroll
            for (int cc = 0; cc < 4; cc++) {
                float4 t = *(const float4*)&Vs[(tc * 4 + cc) * 64 + i];
                vr[cc][0] = t.x; vr[cc][1] = t.y; vr[cc][2] = t.z; vr[cc][3] = t.w;
            }
            #pragma unroll
            for (int r = 0; r < 4; r++) {
                float4 t = *(const float4*)&ps[(i + r) * 64 + tj * 4];
                pr[r][0] = t.x; pr[r][1] = t.y; pr[r][2] = t.z; pr[r][3] = t.w;
            }
            #pragma unroll
            for (int r = 0; r < 4; r++)
                #pragma unroll
                for (int cc = 0; cc < 4; cc++)
                    #pragma unroll
                    for (int jj = 0; jj < 4; jj++)
                        acc[cc][jj] += vr[cc][r] * pr[r][jj];
        }
    }

    const float scale = (a == 0) ? beta[0] : gamma[0];
    const float* xin  = (a == 0) ? x2 : x1;
    float* ob = out + (a == 0 ? (size_t)NB * NC * NN : 0);
    #pragma unroll
    for (int cc = 0; cc < 4; cc++) {
        int c = tc * 4 + cc;
        size_t gi = ((size_t)b * NC + c) * NN + j0 + tj * 4;
        float4 xv = *(const float4*)&xin[gi];
        float4 o;
        o.x = acc[cc][0] * scale + xv.x;
        o.y = acc[cc][1] * scale + xv.y;
        o.z = acc[cc][2] * scale + xv.z;
        o.w = acc[cc][3] * scale + xv.w;
        *(float4*)&ob[gi] = o;
    }
}

// ---------------------------------------------------------------------------
extern "C" void kernel_launch(void* const* d_in, const int* in_sizes, int n_in,
                              void* d_out, int out_size)
{
    (void)in_sizes; (void)n_in; (void)out_size;
    const float* x1   = (const float*)d_in[0];
    const float* x2   = (const float*)d_in[1];
    const float* Wqk1 = (const float*)d_in[2];
    const float* bqk1 = (const float*)d_in[3];
    const float* Wqk2 = (const float*)d_in[4];
    const float* bqk2 = (const float*)d_in[5];
    const float* Wv1  = (const float*)d_in[6];
    const float* bv1  = (const float*)d_in[7];
    const float* Wv2  = (const float*)d_in[8];
    const float* bv2  = (const float*)d_in[9];
    const float* gamma = (const float*)d_in[10];
    const float* beta  = (const float*)d_in[11];
    float* out = (float*)d_out;

    const int proj_smem  = 18592 * sizeof(float);   // 74368 B
    const int stats_smem = 8 * NN * sizeof(float);  // 73728 B
    cudaFuncSetAttribute(k_proj,  cudaFuncAttributeMaxDynamicSharedMemorySize, proj_smem);
    cudaFuncSetAttribute(k_stats, cudaFuncAttributeMaxDynamicSharedMemorySize, stats_smem);

    k_proj<<<dim3(NN / 64, NB), 256, proj_smem>>>(x1, x2, Wqk1, bqk1, Wqk2, bqk2,
                                                  Wv1, bv1, Wv2, bv2);
    k_stats<<<dim3(NN / 256, 2, NB), 256, stats_smem>>>();
    k_apply<<<dim3(NN / 64, 2, NB), 256>>>(x1, x2, gamma, beta, out);
}

// round 10
// speedup vs baseline: 1.9690x; 1.9690x over previous
#include <cuda_runtime.h>
#include <cuda_bf16.h>
#include <cstdint>

#define NB 8
#define NC 64
#define NN 2304     // 48*48
#define NPROJ 160
#define JT 128      // j-tile per CTA in apply
#define IC 64       // i-chunk per mma pass
#define NCH (NN/IC) // 36

// Scratch (device globals: allocation-free rule)
__device__ __align__(16) float g_qk[2][NB][16][NN];   // [attn][b][0-7=q, 8-15=k][n]
__device__ __align__(16) float g_v[2][NB][NC][NN];
__device__ __align__(16) float g_rinv[2][NB][NN];
// bf16 V pre-scaled by rinv: g_vb[a] = v[1-a] * rinv[a]
__device__ __align__(16) __nv_bfloat16 g_vb[2][NB][NC][NN];

#define SW128(o) ((o) ^ (((o) >> 3) & 0x70))

__device__ __forceinline__ void mma16816(float* d, const uint32_t* a,
                                         uint32_t b0, uint32_t b1) {
    asm volatile(
        "mma.sync.aligned.m16n8k16.row.col.f32.bf16.bf16.f32 "
        "{%0,%1,%2,%3}, {%4,%5,%6,%7}, {%8,%9}, {%0,%1,%2,%3};"
        : "+f"(d[0]), "+f"(d[1]), "+f"(d[2]), "+f"(d[3])
        : "r"(a[0]), "r"(a[1]), "r"(a[2]), "r"(a[3]), "r"(b0), "r"(b1));
}

// ---------------------------------------------------------------------------
// Kernel 1: fused 1x1-conv projections (unchanged from R5 passing version).
// ---------------------------------------------------------------------------
__global__ __launch_bounds__(256) void k_proj(
    const float* __restrict__ x1, const float* __restrict__ x2,
    const float* __restrict__ Wqk1, const float* __restrict__ bqk1,
    const float* __restrict__ Wqk2, const float* __restrict__ bqk2,
    const float* __restrict__ Wv1,  const float* __restrict__ bv1,
    const float* __restrict__ Wv2,  const float* __restrict__ bv2)
{
    extern __shared__ float sm[];
    float* xs1 = sm;
    float* xs2 = sm + 4096;
    float* ws  = sm + 8192;
    float* bs  = sm + 18432;
    const int b   = blockIdx.y;
    const int n0  = blockIdx.x * 64;
    const int tid = threadIdx.x;

    for (int idx = tid; idx < NPROJ * 64; idx += 256) {
        int r = idx >> 6, c = idx & 63;
        float w;
        if (r < 16)      w = Wqk1[r * 64 + c];
        else if (r < 32) w = Wqk2[(r - 16) * 64 + c];
        else if (r < 96) w = Wv1[(r - 32) * 64 + c];
        else             w = Wv2[(r - 96) * 64 + c];
        ws[idx] = w;
    }
    if (tid < NPROJ) {
        float bb;
        if (tid < 16)      bb = bqk1[tid];
        else if (tid < 32) bb = bqk2[tid - 16];
        else if (tid < 96) bb = bv1[tid - 32];
        else               bb = bv2[tid - 96];
        bs[tid] = bb;
    }
    for (int idx = tid; idx < 4096; idx += 256) {
        int c = idx >> 6, col = idx & 63;
        long gi = ((long)b * NC + c) * NN + n0 + col;
        xs1[idx] = x1[gi];
        xs2[idx] = x2[gi];
    }
    __syncthreads();

    const int rowg = tid >> 4;
    const int colg = tid & 15;
    float acc[10][4];
    #pragma unroll
    for (int k = 0; k < 10; k++)
        #pragma unroll
        for (int j = 0; j < 4; j++) acc[k][j] = 0.f;

    for (int c = 0; c < 64; c++) {
        float4 xa = *(const float4*)&xs1[c * 64 + colg * 4];
        float4 xb = *(const float4*)&xs2[c * 64 + colg * 4];
        #pragma unroll
        for (int k = 0; k < 10; k++) {
            const bool useb = (k == 1) || (k >= 6);
            float4 xv = useb ? xb : xa;
            float w = ws[(rowg + 16 * k) * 64 + c];
            acc[k][0] += w * xv.x;
            acc[k][1] += w * xv.y;
            acc[k][2] += w * xv.z;
            acc[k][3] += w * xv.w;
        }
    }

    #pragma unroll
    for (int k = 0; k < 10; k++) {
        int r = rowg + 16 * k;
        float bb = bs[r];
        float4 o;
        o.x = acc[k][0] + bb; o.y = acc[k][1] + bb;
        o.z = acc[k][2] + bb; o.w = acc[k][3] + bb;
        float* dst;
        if (k == 0)      dst = &g_qk[0][b][r][n0];
        else if (k == 1) dst = &g_qk[1][b][r - 16][n0];
        else if (k < 6)  dst = &g_v[0][b][r - 32][n0];
        else             dst = &g_v[1][b][r - 96][n0];
        *(float4*)&dst[colg * 4] = o;
    }
}

// ---------------------------------------------------------------------------
// Kernel 2: softmax row sums (no max-subtraction; logits bounded).
// ---------------------------------------------------------------------------
__global__ __launch_bounds__(256) void k_stats()
{
    extern __shared__ float ks[];   // [NN][8]
    const int a = blockIdx.y, b = blockIdx.z;
    const int i = blockIdx.x * 256 + threadIdx.x;
    const float* kb = &g_qk[a][b][8][0];
    for (int idx = threadIdx.x; idx < 8 * NN; idx += 256) {
        int c = idx / NN;
        int n = idx - c * NN;
        ks[n * 8 + c] = kb[idx];
    }
    __syncthreads();
    float q[8];
    #pragma unroll
    for (int c = 0; c < 8; c++) q[c] = g_qk[a][b][c][i];
    const float4* k4 = (const float4*)ks;
    float Z0 = 0.f, Z1 = 0.f, Z2 = 0.f, Z3 = 0.f;
    for (int j = 0; j < NN; j += 4) {
        #pragma unroll
        for (int u = 0; u < 4; u++) {
            float4 a0 = k4[(j + u) * 2];
            float4 a1 = k4[(j + u) * 2 + 1];
            float s = q[0]*a0.x + q[1]*a0.y + q[2]*a0.z + q[3]*a0.w
                    + q[4]*a1.x + q[5]*a1.y + q[6]*a1.z + q[7]*a1.w;
            float e = __expf(s);
            if (u == 0) Z0 += e; else if (u == 1) Z1 += e;
            else if (u == 2) Z2 += e; else Z3 += e;
        }
    }
    g_rinv[a][b][i] = 1.f / ((Z0 + Z1) + (Z2 + Z3));
}

// ---------------------------------------------------------------------------
// Kernel 2b: g_vb[a][b][c][i] = bf16( g_v[1-a][b][c][i] * g_rinv[a][b][i] )
// ---------------------------------------------------------------------------
__global__ __launch_bounds__(64) void k_scalev()
{
    const int i4 = blockIdx.x * 64 + threadIdx.x;  // float4 index
    const int c  = blockIdx.y;
    const int ab = blockIdx.z;
    const int a = ab >> 3, b = ab & 7;
    float4 v = *(const float4*)&g_v[1 - a][b][c][i4 * 4];
    float4 r = *(const float4*)&g_rinv[a][b][i4 * 4];
    float e0 = v.x * r.x, e1 = v.y * r.y, e2 = v.z * r.z, e3 = v.w * r.w;
    uint32_t p0, p1;
    asm("cvt.rn.bf16x2.f32 %0, %1, %2;" : "=r"(p0) : "f"(e1), "f"(e0));
    asm("cvt.rn.bf16x2.f32 %0, %1, %2;" : "=r"(p1) : "f"(e3), "f"(e2));
    *(uint2*)((char*)&g_vb[a][b][c][0] + (size_t)i4 * 8) = make_uint2(p0, p1);
}

// ---------------------------------------------------------------------------
// Kernel 3: HMMA apply. D[j][c] = sum_i exp(q_i.k_j) * (v[c][i]*rinv_i)
//   mma.sync m16n8k16 bf16, register accumulators. P tiles computed SIMT
//   (fp32 s -> exp -> bf16) into SW128 smem; V chunks staged bf16 SW128.
//   out = D*scale + x.
// ---------------------------------------------------------------------------
__global__ __launch_bounds__(256, 2) void k_apply(
    const float* __restrict__ x1, const float* __restrict__ x2,
    const float* __restrict__ gamma, const float* __restrict__ beta,
    float* __restrict__ out)
{
    __shared__ __align__(1024) unsigned char ps[JT * 128];   // [128 j][64 i] bf16 SW128
    __shared__ __align__(1024) unsigned char vs[64 * 128];   // [64 c][64 i]  bf16 SW128
    __shared__ __align__(16)   float kt[JT * 8];             // [j][c]
    __shared__ __align__(16)   float qs[8 * IC];             // [c][i]

    const int a  = blockIdx.y, b = blockIdx.z;
    const int j0 = blockIdx.x * JT;
    const int tid = threadIdx.x;
    const int wid = tid >> 5, lid = tid & 31;

    // K block for this j-tile
    for (int idx = tid; idx < JT * 8; idx += 256) {
        int c = idx >> 7, j = idx & 127;
        kt[j * 8 + c] = g_qk[a][b][8 + c][j0 + j];
    }

    const int jb  = tid >> 3;   // P-gen: 4 j rows jb*4..
    const int ibx = tid & 7;    //        8 i cols ibx*8..
    const int grp = lid >> 2, qid = lid & 3;   // mma lane decomposition

    float acc[8][4];
    #pragma unroll
    for (int u = 0; u < 8; u++)
        #pragma unroll
        for (int v = 0; v < 4; v++) acc[u][v] = 0.f;

    const __nv_bfloat16* vsrc = &g_vb[a][b][0][0];

    for (int ch = 0; ch < NCH; ch++) {
        const int i0 = ch * IC;
        __syncthreads();   // kt ready (ch 0) / previous mma reads done

        // stage V' chunk [64 c][64 i] -> SW128
        for (int idx = tid; idx < 512; idx += 256) {
            int c = idx >> 3, seg = idx & 7;
            uint4 v = *(const uint4*)((const char*)vsrc + ((size_t)c * NN + i0) * 2 + seg * 16);
            *(uint4*)(vs + SW128((uint32_t)(c * 128 + seg * 16))) = v;
        }
        // stage Q chunk [8 c][64 i]
        for (int idx = tid; idx < 512; idx += 256) {
            int c = idx >> 6, i = idx & 63;
            qs[c * 64 + i] = g_qk[a][b][c][i0 + i];
        }
        __syncthreads();

        // P tile: s = q.k, p = exp(s) -> bf16 [j][i] SW128
        #pragma unroll
        for (int ih = 0; ih < 2; ih++) {
            const int it0 = ibx * 8 + ih * 4;
            float4 qv[8];
            #pragma unroll
            for (int c = 0; c < 8; c++) qv[c] = *(const float4*)&qs[c * 64 + it0];
            #pragma unroll
            for (int jj = 0; jj < 4; jj++) {
                const int j = jb * 4 + jj;
                float4 ka = *(const float4*)&kt[j * 8];       // broadcast (8 lanes same j)
                float4 kc = *(const float4*)&kt[j * 8 + 4];
                float sx = qv[0].x*ka.x + qv[1].x*ka.y + qv[2].x*ka.z + qv[3].x*ka.w
                         + qv[4].x*kc.x + qv[5].x*kc.y + qv[6].x*kc.z + qv[7].x*kc.w;
                float sy = qv[0].y*ka.x + qv[1].y*ka.y + qv[2].y*ka.z + qv[3].y*ka.w
                         + qv[4].y*kc.x + qv[5].y*kc.y + qv[6].y*kc.z + qv[7].y*kc.w;
                float sz = qv[0].z*ka.x + qv[1].z*ka.y + qv[2].z*ka.z + qv[3].z*ka.w
                         + qv[4].z*kc.x + qv[5].z*kc.y + qv[6].z*kc.z + qv[7].z*kc.w;
                float sw = qv[0].w*ka.x + qv[1].w*ka.y + qv[2].w*ka.z + qv[3].w*ka.w
                         + qv[4].w*kc.x + qv[5].w*kc.y + qv[6].w*kc.z + qv[7].w*kc.w;
                float ex = __expf(sx), ey = __expf(sy);
                float ez = __expf(sz), ew = __expf(sw);
                uint32_t p0, p1;
                asm("cvt.rn.bf16x2.f32 %0, %1, %2;" : "=r"(p0) : "f"(ey), "f"(ex));
                asm("cvt.rn.bf16x2.f32 %0, %1, %2;" : "=r"(p1) : "f"(ew), "f"(ez));
                *(uint2*)(ps + SW128((uint32_t)(j * 128 + it0 * 2))) = make_uint2(p0, p1);
            }
        }
        __syncthreads();

        // HMMA: warp wid owns j rows [wid*16, wid*16+16), all 64 c
        #pragma unroll
        for (int k = 0; k < 4; k++) {
            const int i2 = k * 32 + qid * 4;     // byte offset along i
            const int jr = wid * 16 + grp;
            uint32_t afr[4];
            afr[0] = *(const uint32_t*)(ps + SW128((uint32_t)( jr      * 128 + i2)));
            afr[1] = *(const uint32_t*)(ps + SW128((uint32_t)((jr + 8) * 128 + i2)));
            afr[2] = *(const uint32_t*)(ps + SW128((uint32_t)( jr      * 128 + i2 + 16)));
            afr[3] = *(const uint32_t*)(ps + SW128((uint32_t)((jr + 8) * 128 + i2 + 16)));
            #pragma unroll
            for (int cc = 0; cc < 8; cc++) {
                const int cr = cc * 8 + grp;
                uint32_t b0 = *(const uint32_t*)(vs + SW128((uint32_t)(cr * 128 + i2)));
                uint32_t b1 = *(const uint32_t*)(vs + SW128((uint32_t)(cr * 128 + i2 + 16)));
                mma16816(acc[cc], afr, b0, b1);
            }
        }
    }

    // Epilogue: D fragment -> out = D*scale + x
    const float scale = (a == 0) ? beta[0] : gamma[0];
    const float* xin  = (a == 0) ? x2 : x1;
    float* ob = out + (a == 0 ? (size_t)NB * NC * NN : 0);
    const int jlo = j0 + wid * 16 + grp;
    #pragma unroll
    for (int cc = 0; cc < 8; cc++) {
        const int c0 = cc * 8 + qid * 2;
        size_t g00 = ((size_t)b * NC + c0) * NN + jlo;
        ob[g00]          = acc[cc][0] * scale + xin[g00];
        ob[g00 + NN]     = acc[cc][1] * scale + xin[g00 + NN];
        ob[g00 + 8]      = acc[cc][2] * scale + xin[g00 + 8];
        ob[g00 + NN + 8] = acc[cc][3] * scale + xin[g00 + NN + 8];
    }
}

// ---------------------------------------------------------------------------
extern "C" void kernel_launch(void* const* d_in, const int* in_sizes, int n_in,
                              void* d_out, int out_size)
{
    (void)in_sizes; (void)n_in; (void)out_size;
    const float* x1   = (const float*)d_in[0];
    const float* x2   = (const float*)d_in[1];
    const float* Wqk1 = (const float*)d_in[2];
    const float* bqk1 = (const float*)d_in[3];
    const float* Wqk2 = (const float*)d_in[4];
    const float* bqk2 = (const float*)d_in[5];
    const float* Wv1  = (const float*)d_in[6];
    const float* bv1  = (const float*)d_in[7];
    const float* Wv2  = (const float*)d_in[8];
    const float* bv2  = (const float*)d_in[9];
    const float* gamma = (const float*)d_in[10];
    const float* beta  = (const float*)d_in[11];
    float* out = (float*)d_out;

    const int proj_smem  = 18592 * sizeof(float);
    const int stats_smem = 8 * NN * sizeof(float);
    cudaFuncSetAttribute(k_proj,  cudaFuncAttributeMaxDynamicSharedMemorySize, proj_smem);
    cudaFuncSetAttribute(k_stats, cudaFuncAttributeMaxDynamicSharedMemorySize, stats_smem);

    k_proj<<<dim3(NN / 64, NB), 256, proj_smem>>>(x1, x2, Wqk1, bqk1, Wqk2, bqk2,
                                                  Wv1, bv1, Wv2, bv2);
    k_stats<<<dim3(NN / 256, 2, NB), 256, stats_smem>>>();
    k_scalev<<<dim3(NN / 256, NC, 2 * NB), 64>>>();
    k_apply<<<dim3(NN / JT, 2, NB), 256>>>(x1, x2, gamma, beta, out);
}

// round 15
// speedup vs baseline: 2.4417x; 1.2401x over previous
#include <cuda_runtime.h>
#include <cuda_bf16.h>
#include <cstdint>

#define NB 8
#define NC 64
#define NN 2304     // 48*48
#define NPROJ 160
#define JT 128      // j-tile per CTA in apply
#define IC 64       // i-chunk per mma pass
#define NCH (NN/IC) // 36
#define QS 12       // Q smem stride in floats (48B: 16B-aligned float4, bank-clean)

// Scratch (device globals: allocation-free rule)
__device__ __align__(16) float g_qk[2][NB][16][NN];   // [attn][b][0-7=q, 8-15=k][n]
__device__ __align__(16) float g_v[2][NB][NC][NN];
// bf16 V pre-scaled by rinv: g_vb[a] = v[1-a] * rinv[a]
__device__ __align__(16) __nv_bfloat16 g_vb[2][NB][NC][NN];

#define SW128(o) ((o) ^ (((o) >> 3) & 0x70))

__device__ __forceinline__ void mma16816(float* d, const uint32_t* a,
                                         uint32_t b0, uint32_t b1) {
    asm volatile(
        "mma.sync.aligned.m16n8k16.row.col.f32.bf16.bf16.f32 "
        "{%0,%1,%2,%3}, {%4,%5,%6,%7}, {%8,%9}, {%0,%1,%2,%3};"
        : "+f"(d[0]), "+f"(d[1]), "+f"(d[2]), "+f"(d[3])
        : "r"(a[0]), "r"(a[1]), "r"(a[2]), "r"(a[3]), "r"(b0), "r"(b1));
}

// ---------------------------------------------------------------------------
// Kernel 1: fused 1x1-conv projections (unchanged from passing R10 version).
// ---------------------------------------------------------------------------
__global__ __launch_bounds__(256) void k_proj(
    const float* __restrict__ x1, const float* __restrict__ x2,
    const float* __restrict__ Wqk1, const float* __restrict__ bqk1,
    const float* __restrict__ Wqk2, const float* __restrict__ bqk2,
    const float* __restrict__ Wv1,  const float* __restrict__ bv1,
    const float* __restrict__ Wv2,  const float* __restrict__ bv2)
{
    extern __shared__ float sm[];
    float* xs1 = sm;
    float* xs2 = sm + 4096;
    float* ws  = sm + 8192;
    float* bs  = sm + 18432;
    const int b   = blockIdx.y;
    const int n0  = blockIdx.x * 64;
    const int tid = threadIdx.x;

    for (int idx = tid; idx < NPROJ * 64; idx += 256) {
        int r = idx >> 6, c = idx & 63;
        float w;
        if (r < 16)      w = Wqk1[r * 64 + c];
        else if (r < 32) w = Wqk2[(r - 16) * 64 + c];
        else if (r < 96) w = Wv1[(r - 32) * 64 + c];
        else             w = Wv2[(r - 96) * 64 + c];
        ws[idx] = w;
    }
    if (tid < NPROJ) {
        float bb;
        if (tid < 16)      bb = bqk1[tid];
        else if (tid < 32) bb = bqk2[tid - 16];
        else if (tid < 96) bb = bv1[tid - 32];
        else               bb = bv2[tid - 96];
        bs[tid] = bb;
    }
    for (int idx = tid; idx < 4096; idx += 256) {
        int c = idx >> 6, col = idx & 63;
        long gi = ((long)b * NC + c) * NN + n0 + col;
        xs1[idx] = x1[gi];
        xs2[idx] = x2[gi];
    }
    __syncthreads();

    const int rowg = tid >> 4;
    const int colg = tid & 15;
    float acc[10][4];
    #pragma unroll
    for (int k = 0; k < 10; k++)
        #pragma unroll
        for (int j = 0; j < 4; j++) acc[k][j] = 0.f;

    for (int c = 0; c < 64; c++) {
        float4 xa = *(const float4*)&xs1[c * 64 + colg * 4];
        float4 xb = *(const float4*)&xs2[c * 64 + colg * 4];
        #pragma unroll
        for (int k = 0; k < 10; k++) {
            const bool useb = (k == 1) || (k >= 6);
            float4 xv = useb ? xb : xa;
            float w = ws[(rowg + 16 * k) * 64 + c];
            acc[k][0] += w * xv.x;
            acc[k][1] += w * xv.y;
            acc[k][2] += w * xv.z;
            acc[k][3] += w * xv.w;
        }
    }

    #pragma unroll
    for (int k = 0; k < 10; k++) {
        int r = rowg + 16 * k;
        float bb = bs[r];
        float4 o;
        o.x = acc[k][0] + bb; o.y = acc[k][1] + bb;
        o.z = acc[k][2] + bb; o.w = acc[k][3] + bb;
        float* dst;
        if (k == 0)      dst = &g_qk[0][b][r][n0];
        else if (k == 1) dst = &g_qk[1][b][r - 16][n0];
        else if (k < 6)  dst = &g_v[0][b][r - 32][n0];
        else             dst = &g_v[1][b][r - 96][n0];
        *(float4*)&dst[colg * 4] = o;
    }
}

// ---------------------------------------------------------------------------
// Kernel 2: softmax row sums + fused V-scaling.
//   rinv_i = 1/sum_j exp(q_i.k_j)  (no max-subtraction; logits bounded)
//   then g_vb[a][b][c][i] = bf16( g_v[1-a][b][c][i] * rinv_i )  (i in block range)
// ---------------------------------------------------------------------------
__global__ __launch_bounds__(256) void k_stats()
{
    extern __shared__ float sm2[];
    float* ks    = sm2;            // [NN][8]
    float* srinv = sm2 + 8 * NN;   // [256]
    const int a = blockIdx.y, b = blockIdx.z;
    const int ibase = blockIdx.x * 256;
    const int i = ibase + threadIdx.x;
    const float* kb = &g_qk[a][b][8][0];
    for (int idx = threadIdx.x; idx < 8 * NN; idx += 256) {
        int c = idx / NN;
        int n = idx - c * NN;
        ks[n * 8 + c] = kb[idx];
    }
    __syncthreads();
    float q[8];
    #pragma unroll
    for (int c = 0; c < 8; c++) q[c] = g_qk[a][b][c][i];
    const float4* k4 = (const float4*)ks;
    float Z0 = 0.f, Z1 = 0.f, Z2 = 0.f, Z3 = 0.f;
    for (int j = 0; j < NN; j += 4) {
        #pragma unroll
        for (int u = 0; u < 4; u++) {
            float4 a0 = k4[(j + u) * 2];
            float4 a1 = k4[(j + u) * 2 + 1];
            float s = q[0]*a0.x + q[1]*a0.y + q[2]*a0.z + q[3]*a0.w
                    + q[4]*a1.x + q[5]*a1.y + q[6]*a1.z + q[7]*a1.w;
            float e = __expf(s);
            if (u == 0) Z0 += e; else if (u == 1) Z1 += e;
            else if (u == 2) Z2 += e; else Z3 += e;
        }
    }
    srinv[threadIdx.x] = 1.f / ((Z0 + Z1) + (Z2 + Z3));
    __syncthreads();

    // fused scalev epilogue: 64 c x 128 i-pairs for this block's i-range
    const float* vsb = &g_v[1 - a][b][0][0];
    char* vbb = (char*)&g_vb[a][b][0][0];
    #pragma unroll 4
    for (int t = 0; t < 32; t++) {
        int idx = threadIdx.x + t * 256;     // 0..8191
        int c = idx >> 7, p = idx & 127;
        size_t off = (size_t)c * NN + ibase + p * 2;
        float2 v = *(const float2*)&vsb[off];
        float r0 = srinv[p * 2], r1 = srinv[p * 2 + 1];
        uint32_t pk;
        asm("cvt.rn.bf16x2.f32 %0, %1, %2;" : "=r"(pk) : "f"(v.y * r1), "f"(v.x * r0));
        *(uint32_t*)(vbb + off * 2) = pk;
    }
}

// ---------------------------------------------------------------------------
// Kernel 3: HMMA apply, fragment-direct P generation.
//   D[j][c] = sum_i exp(q_i.k_j) * (v[c][i]*rinv_i);  out = D*scale + x.
//   Each lane computes its mma A-fragment values (s -> exp -> bf16x2) in
//   registers; V chunks staged bf16 SW128, double-buffered; 1 sync/chunk.
//   Q staged [i][c] with stride QS=12 floats: float4-aligned AND bank-clean.
// ---------------------------------------------------------------------------
__global__ __launch_bounds__(256, 2) void k_apply(
    const float* __restrict__ x1, const float* __restrict__ x2,
    const float* __restrict__ gamma, const float* __restrict__ beta,
    float* __restrict__ out)
{
    __shared__ __align__(1024) unsigned char vs[2][64 * 128];  // [c][i] bf16 SW128
    __shared__ __align__(16)   float qs[2][64 * QS];           // [i][c] stride 12

    const int a  = blockIdx.y, b = blockIdx.z;
    const int j0 = blockIdx.x * JT;
    const int tid = threadIdx.x;
    const int wid = tid >> 5, lid = tid & 31;
    const int grp = lid >> 2, qid = lid & 3;
    const int jr  = wid * 16 + grp;          // local j row (and jr+8)

    // K rows for this lane's two j's: loop-invariant registers
    float kr0[8], kr1[8];
    #pragma unroll
    for (int c = 0; c < 8; c++) {
        kr0[c] = g_qk[a][b][8 + c][j0 + jr];
        kr1[c] = g_qk[a][b][8 + c][j0 + jr + 8];
    }

    float acc[8][4];
    #pragma unroll
    for (int u = 0; u < 8; u++)
        #pragma unroll
        for (int v = 0; v < 4; v++) acc[u][v] = 0.f;

    const __nv_bfloat16* vsrc = &g_vb[a][b][0][0];
    const float* qsrc = &g_qk[a][b][0][0];

    auto stage = [&](int ch, int buf) {
        const int i0 = ch * IC;
        #pragma unroll
        for (int t = 0; t < 2; t++) {
            int idx = tid + t * 256;
            int c = idx >> 3, seg = idx & 7;
            uint4 v = *(const uint4*)((const char*)vsrc + ((size_t)c * NN + i0) * 2 + seg * 16);
            *(uint4*)(&vs[buf][0] + SW128((uint32_t)(c * 128 + seg * 16))) = v;
        }
        #pragma unroll
        for (int t = 0; t < 2; t++) {
            int idx = tid + t * 256;
            int c = idx >> 6, i = idx & 63;
            qs[buf][i * QS + c] = qsrc[(size_t)c * NN + i0 + i];
        }
    };

    stage(0, 0);
    __syncthreads();

    for (int ch = 0; ch < NCH; ch++) {
        const int buf = ch & 1;
        if (ch + 1 < NCH) stage(ch + 1, buf ^ 1);   // overlap next-chunk loads

        #pragma unroll
        for (int k = 0; k < 4; k++) {
            const int ib = k * 16 + qid * 2;
            float e[8];
            #pragma unroll
            for (int u = 0; u < 4; u++) {
                const int i = ib + (u >> 1) * 8 + (u & 1);  // ib, ib+1, ib+8, ib+9
                float4 qa = *(const float4*)&qs[buf][i * QS];
                float4 qb = *(const float4*)&qs[buf][i * QS + 4];
                float s0 = qa.x*kr0[0] + qa.y*kr0[1] + qa.z*kr0[2] + qa.w*kr0[3]
                         + qb.x*kr0[4] + qb.y*kr0[5] + qb.z*kr0[6] + qb.w*kr0[7];
                float s1 = qa.x*kr1[0] + qa.y*kr1[1] + qa.z*kr1[2] + qa.w*kr1[3]
                         + qb.x*kr1[4] + qb.y*kr1[5] + qb.z*kr1[6] + qb.w*kr1[7];
                e[u * 2]     = __expf(s0);   // P(jr,   i)
                e[u * 2 + 1] = __expf(s1);   // P(jr+8, i)
            }
            uint32_t afr[4];
            // a0:(jr,ib|ib+1) a1:(jr+8,..) a2:(jr,ib+8|ib+9) a3:(jr+8,..); lo=first i
            asm("cvt.rn.bf16x2.f32 %0, %1, %2;" : "=r"(afr[0]) : "f"(e[2]), "f"(e[0]));
            asm("cvt.rn.bf16x2.f32 %0, %1, %2;" : "=r"(afr[1]) : "f"(e[3]), "f"(e[1]));
            asm("cvt.rn.bf16x2.f32 %0, %1, %2;" : "=r"(afr[2]) : "f"(e[6]), "f"(e[4]));
            asm("cvt.rn.bf16x2.f32 %0, %1, %2;" : "=r"(afr[3]) : "f"(e[7]), "f"(e[5]));

            const uint32_t bb = (uint32_t)(k * 32 + qid * 4);
            #pragma unroll
            for (int cc = 0; cc < 8; cc++) {
                const uint32_t cr = (uint32_t)(cc * 8 + grp) * 128;
                uint32_t b0 = *(const uint32_t*)(&vs[buf][0] + SW128(cr + bb));
                uint32_t b1 = *(const uint32_t*)(&vs[buf][0] + SW128(cr + bb + 16));
                mma16816(acc[cc], afr, b0, b1);
            }
        }
        __syncthreads();   // staging of ch+1 complete; reads of buf done
    }

    // Epilogue: D fragment -> out = D*scale + x  (layout identical to R10)
    const float scale = (a == 0) ? beta[0] : gamma[0];
    const float* xin  = (a == 0) ? x2 : x1;
    float* ob = out + (a == 0 ? (size_t)NB * NC * NN : 0);
    const int jlo = j0 + jr;
    #pragma unroll
    for (int cc = 0; cc < 8; cc++) {
        const int c0 = cc * 8 + qid * 2;
        size_t g00 = ((size_t)b * NC + c0) * NN + jlo;
        ob[g00]          = acc[cc][0] * scale + xin[g00];
        ob[g00 + NN]     = acc[cc][1] * scale + xin[g00 + NN];
        ob[g00 + 8]      = acc[cc][2] * scale + xin[g00 + 8];
        ob[g00 + NN + 8] = acc[cc][3] * scale + xin[g00 + NN + 8];
    }
}

// ---------------------------------------------------------------------------
extern "C" void kernel_launch(void* const* d_in, const int* in_sizes, int n_in,
                              void* d_out, int out_size)
{
    (void)in_sizes; (void)n_in; (void)out_size;
    const float* x1   = (const float*)d_in[0];
    const float* x2   = (const float*)d_in[1];
    const float* Wqk1 = (const float*)d_in[2];
    const float* bqk1 = (const float*)d_in[3];
    const float* Wqk2 = (const float*)d_in[4];
    const float* bqk2 = (const float*)d_in[5];
    const float* Wv1  = (const float*)d_in[6];
    const float* bv1  = (const float*)d_in[7];
    const float* Wv2  = (const float*)d_in[8];
    const float* bv2  = (const float*)d_in[9];
    const float* gamma = (const float*)d_in[10];
    const float* beta  = (const float*)d_in[11];
    float* out = (float*)d_out;

    const int proj_smem  = 18592 * sizeof(float);
    const int stats_smem = (8 * NN + 256) * sizeof(float);
    cudaFuncSetAttribute(k_proj,  cudaFuncAttributeMaxDynamicSharedMemorySize, proj_smem);
    cudaFuncSetAttribute(k_stats, cudaFuncAttributeMaxDynamicSharedMemorySize, stats_smem);

    k_proj<<<dim3(NN / 64, NB), 256, proj_smem>>>(x1, x2, Wqk1, bqk1, Wqk2, bqk2,
                                                  Wv1, bv1, Wv2, bv2);
    k_stats<<<dim3(NN / 256, 2, NB), 256, stats_smem>>>();
    k_apply<<<dim3(NN / JT, 2, NB), 256>>>(x1, x2, gamma, beta, out);
}

// round 16
// speedup vs baseline: 4.8923x; 2.0036x over previous
#include <cuda_runtime.h>
#include <cuda_bf16.h>
#include <cstdint>

#define NB 8
#define NC 64
#define NN 2304     // 48*48
#define NPROJ 160
#define JT 128      // j-tile per CTA in apply
#define IC 64       // i-chunk per mma pass
#define NCH (NN/IC) // 36
#define QSTR 72     // apply Q smem stride (floats): 8*qid+grp banks all distinct

// Scratch (device globals: allocation-free rule)
__device__ __align__(16) float g_qk[2][NB][16][NN];   // [attn][b][0-7=q, 8-15=k][n]
__device__ __align__(16) float g_v[2][NB][NC][NN];
// bf16 V pre-scaled by rinv: g_vb[a] = v[1-a] * rinv[a]
__device__ __align__(16) __nv_bfloat16 g_vb[2][NB][NC][NN];

#define SW128(o) ((o) ^ (((o) >> 3) & 0x70))

__device__ __forceinline__ uint32_t f2tf32(float x) {
    uint32_t r;
    asm("cvt.rna.tf32.f32 %0, %1;" : "=r"(r) : "f"(x));
    return r;
}
// bf16 O-MMA: D += A(P) * B(V)
__device__ __forceinline__ void mma16816(float* d, const uint32_t* a,
                                         uint32_t b0, uint32_t b1) {
    asm volatile(
        "mma.sync.aligned.m16n8k16.row.col.f32.bf16.bf16.f32 "
        "{%0,%1,%2,%3}, {%4,%5,%6,%7}, {%8,%9}, {%0,%1,%2,%3};"
        : "+f"(d[0]), "+f"(d[1]), "+f"(d[2]), "+f"(d[3])
        : "r"(a[0]), "r"(a[1]), "r"(a[2]), "r"(a[3]), "r"(b0), "r"(b1));
}
// tf32 S-MMA: D = A * B + 0   (m16n8k8)
__device__ __forceinline__ void mma1688tf(float* d, const uint32_t* a,
                                          uint32_t b0, uint32_t b1) {
    asm volatile(
        "mma.sync.aligned.m16n8k8.row.col.f32.tf32.tf32.f32 "
        "{%0,%1,%2,%3}, {%4,%5,%6,%7}, {%8,%9}, {%10,%10,%10,%10};"
        : "=f"(d[0]), "=f"(d[1]), "=f"(d[2]), "=f"(d[3])
        : "r"(a[0]), "r"(a[1]), "r"(a[2]), "r"(a[3]), "r"(b0), "r"(b1),
          "f"(0.0f));
}

// ---------------------------------------------------------------------------
// Kernel 1: fused 1x1-conv projections. 512 threads, 128-n tile, grid = one
// wave (144 CTAs): halves weight reloads, removes wave-tail imbalance.
// ---------------------------------------------------------------------------
__global__ __launch_bounds__(512) void k_proj(
    const float* __restrict__ x1, const float* __restrict__ x2,
    const float* __restrict__ Wqk1, const float* __restrict__ bqk1,
    const float* __restrict__ Wqk2, const float* __restrict__ bqk2,
    const float* __restrict__ Wv1,  const float* __restrict__ bv1,
    const float* __restrict__ Wv2,  const float* __restrict__ bv2)
{
    extern __shared__ float sm[];
    float* xs1 = sm;              // [64][128]
    float* xs2 = sm + 8192;      // [64][128]
    float* ws  = sm + 16384;     // [160][64]
    float* bs  = sm + 26624;     // [160]
    const int b   = blockIdx.y;
    const int n0  = blockIdx.x * 128;
    const int tid = threadIdx.x;

    for (int idx = tid; idx < NPROJ * 64; idx += 512) {
        int r = idx >> 6, c = idx & 63;
        float w;
        if (r < 16)      w = Wqk1[r * 64 + c];
        else if (r < 32) w = Wqk2[(r - 16) * 64 + c];
        else if (r < 96) w = Wv1[(r - 32) * 64 + c];
        else             w = Wv2[(r - 96) * 64 + c];
        ws[idx] = w;
    }
    if (tid < NPROJ) {
        float bb;
        if (tid < 16)      bb = bqk1[tid];
        else if (tid < 32) bb = bqk2[tid - 16];
        else if (tid < 96) bb = bv1[tid - 32];
        else               bb = bv2[tid - 96];
        bs[tid] = bb;
    }
    for (int idx = tid; idx < 8192; idx += 512) {
        int c = idx >> 7, col = idx & 127;
        long gi = ((long)b * NC + c) * NN + n0 + col;
        xs1[idx] = x1[gi];
        xs2[idx] = x2[gi];
    }
    __syncthreads();

    const int rowg = tid >> 5;   // 0..15 (uniform per warp -> ws broadcast)
    const int colg = tid & 31;   // 0..31, 4 cols each
    float acc[10][4];
    #pragma unroll
    for (int k = 0; k < 10; k++)
        #pragma unroll
        for (int j = 0; j < 4; j++) acc[k][j] = 0.f;

    for (int c = 0; c < 64; c++) {
        float4 xa = *(const float4*)&xs1[c * 128 + colg * 4];
        float4 xb = *(const float4*)&xs2[c * 128 + colg * 4];
        #pragma unroll
        for (int k = 0; k < 10; k++) {
            const bool useb = (k == 1) || (k >= 6);
            float4 xv = useb ? xb : xa;
            float w = ws[(rowg + 16 * k) * 64 + c];
            acc[k][0] += w * xv.x;
            acc[k][1] += w * xv.y;
            acc[k][2] += w * xv.z;
            acc[k][3] += w * xv.w;
        }
    }

    #pragma unroll
    for (int k = 0; k < 10; k++) {
        int r = rowg + 16 * k;
        float bb = bs[r];
        float4 o;
        o.x = acc[k][0] + bb; o.y = acc[k][1] + bb;
        o.z = acc[k][2] + bb; o.w = acc[k][3] + bb;
        float* dst;
        if (k == 0)      dst = &g_qk[0][b][r][n0];
        else if (k == 1) dst = &g_qk[1][b][r - 16][n0];
        else if (k < 6)  dst = &g_v[0][b][r - 32][n0];
        else             dst = &g_v[1][b][r - 96][n0];
        *(float4*)&dst[colg * 4] = o;
    }
}

// ---------------------------------------------------------------------------
// Kernel 2: softmax row sums via tf32 S-MMA + fused V-scaling.
//   Warp owns 16 i-rows (A-frag loop-invariant); sweeps j in 8-wide B blocks
//   from smem K; exp D-frags, row-sum, butterfly over qid -> Z.
//   Then g_vb = bf16(v * rinv) for this CTA's 128-i range.
// ---------------------------------------------------------------------------
__global__ __launch_bounds__(256) void k_stats()
{
    extern __shared__ float sm2[];
    float* ks    = sm2;            // [NN][8] tf32 bits
    float* srinv = sm2 + 8 * NN;   // [128]
    const int a = blockIdx.y, b = blockIdx.z;
    const int i0 = blockIdx.x * 128;
    const int tid = threadIdx.x;
    const int wid = tid >> 5, lid = tid & 31;
    const int grp = lid >> 2, qid = lid & 3;
    const int ir  = wid * 16 + grp;            // local i row (and ir+8)

    // K -> smem, tf32-rounded (consistent with k_apply)
    for (int idx = tid; idx < 8 * NN; idx += 256) {
        int c = idx / NN;
        int n = idx - c * NN;
        ks[n * 8 + c] = __uint_as_float(f2tf32(g_qk[a][b][8 + c][n]));
    }
    // A-frag: Q rows i0+ir / i0+ir+8, ch qid / qid+4 (tf32)
    uint32_t qa[4];
    qa[0] = f2tf32(g_qk[a][b][qid][i0 + ir]);
    qa[1] = f2tf32(g_qk[a][b][qid][i0 + ir + 8]);
    qa[2] = f2tf32(g_qk[a][b][qid + 4][i0 + ir]);
    qa[3] = f2tf32(g_qk[a][b][qid + 4][i0 + ir + 8]);
    __syncthreads();

    float z0 = 0.f, z1 = 0.f;
    for (int jb = 0; jb < NN; jb += 8) {
        uint32_t b0 = __float_as_uint(ks[(jb + grp) * 8 + qid]);
        uint32_t b1 = __float_as_uint(ks[(jb + grp) * 8 + qid + 4]);
        float d[4];
        mma1688tf(d, qa, b0, b1);
        z0 += __expf(d[0]) + __expf(d[1]);   // row ir,   j = jb+2qid, +1
        z1 += __expf(d[2]) + __expf(d[3]);   // row ir+8
    }
    // reduce over the 4 qid lanes (consecutive lids within grp)
    z0 += __shfl_xor_sync(0xFFFFFFFFu, z0, 1);
    z0 += __shfl_xor_sync(0xFFFFFFFFu, z0, 2);
    z1 += __shfl_xor_sync(0xFFFFFFFFu, z1, 1);
    z1 += __shfl_xor_sync(0xFFFFFFFFu, z1, 2);
    if (qid == 0) {
        srinv[ir]     = 1.f / z0;
        srinv[ir + 8] = 1.f / z1;
    }
    __syncthreads();

    // fused scalev: 64 c x 64 i-pairs for [i0, i0+128)
    const float* vsb = &g_v[1 - a][b][0][0];
    char* vbb = (char*)&g_vb[a][b][0][0];
    #pragma unroll 4
    for (int t = 0; t < 16; t++) {
        int idx = tid + t * 256;             // 0..4095
        int c = idx >> 6, p = idx & 63;
        size_t off = (size_t)c * NN + i0 + p * 2;
        float2 v = *(const float2*)&vsb[off];
        float r0 = srinv[p * 2], r1 = srinv[p * 2 + 1];
        uint32_t pk;
        asm("cvt.rn.bf16x2.f32 %0, %1, %2;" : "=r"(pk) : "f"(v.y * r1), "f"(v.x * r0));
        *(uint32_t*)(vbb + off * 2) = pk;
    }
}

// ---------------------------------------------------------------------------
// Kernel 3: HMMA apply with tf32 S-MMA logits (flash-attention layout reuse:
// S-MMA D-frag == O-MMA A-frag).  D[j][c] = sum_i exp(q_i.k_j)*(v[c][i]*rinv_i)
// V chunks bf16 SW128 double-buffered; Q chunks tf32 [ch][QSTR]; 1 sync/chunk.
// ---------------------------------------------------------------------------
__global__ __launch_bounds__(256, 2) void k_apply(
    const float* __restrict__ x1, const float* __restrict__ x2,
    const float* __restrict__ gamma, const float* __restrict__ beta,
    float* __restrict__ out)
{
    __shared__ __align__(1024) unsigned char vs[2][64 * 128];  // [c][i] bf16 SW128
    __shared__ __align__(16)   float qs[2][8 * QSTR];          // [ch][i] tf32 bits

    const int a  = blockIdx.y, b = blockIdx.z;
    const int j0 = blockIdx.x * JT;
    const int tid = threadIdx.x;
    const int wid = tid >> 5, lid = tid & 31;
    const int grp = lid >> 2, qid = lid & 3;
    const int jr  = wid * 16 + grp;          // local j row (and jr+8)

    // K A-frag (tf32, loop-invariant): rows jr/jr+8, ch qid/qid+4
    uint32_t ka[4];
    ka[0] = f2tf32(g_qk[a][b][8 + qid][j0 + jr]);
    ka[1] = f2tf32(g_qk[a][b][8 + qid][j0 + jr + 8]);
    ka[2] = f2tf32(g_qk[a][b][8 + qid + 4][j0 + jr]);
    ka[3] = f2tf32(g_qk[a][b][8 + qid + 4][j0 + jr + 8]);

    float acc[8][4];
    #pragma unroll
    for (int u = 0; u < 8; u++)
        #pragma unroll
        for (int v = 0; v < 4; v++) acc[u][v] = 0.f;

    const __nv_bfloat16* vsrc = &g_vb[a][b][0][0];
    const float* qsrc = &g_qk[a][b][0][0];

    auto stage = [&](int ch, int buf) {
        const int i0 = ch * IC;
        #pragma unroll
        for (int t = 0; t < 2; t++) {
            int idx = tid + t * 256;
            int c = idx >> 3, seg = idx & 7;
            uint4 v = *(const uint4*)((const char*)vsrc + ((size_t)c * NN + i0) * 2 + seg * 16);
            *(uint4*)(&vs[buf][0] + SW128((uint32_t)(c * 128 + seg * 16))) = v;
        }
        #pragma unroll
        for (int t = 0; t < 2; t++) {
            int idx = tid + t * 256;
            int c = idx >> 6, i = idx & 63;
            qs[buf][c * QSTR + i] = __uint_as_float(f2tf32(qsrc[(size_t)c * NN + i0 + i]));
        }
    };

    stage(0, 0);
    __syncthreads();

    for (int ch = 0; ch < NCH; ch++) {
        const int buf = ch & 1;
        if (ch + 1 < NCH) stage(ch + 1, buf ^ 1);   // overlap next-chunk loads

        #pragma unroll
        for (int k = 0; k < 4; k++) {
            const int ibase = k * 16;
            // S-MMA #1: i-block [ibase, ibase+8)
            uint32_t b0 = __float_as_uint(qs[buf][qid * QSTR + ibase + grp]);
            uint32_t b1 = __float_as_uint(qs[buf][(qid + 4) * QSTR + ibase + grp]);
            float d0[4];
            mma1688tf(d0, ka, b0, b1);
            // S-MMA #2: i-block [ibase+8, ibase+16)
            uint32_t b2 = __float_as_uint(qs[buf][qid * QSTR + ibase + 8 + grp]);
            uint32_t b3 = __float_as_uint(qs[buf][(qid + 4) * QSTR + ibase + 8 + grp]);
            float d1[4];
            mma1688tf(d1, ka, b2, b3);

            // exp -> bf16x2 A-frag (S D-frag layout == O A-frag layout)
            float e0 = __expf(d0[0]), e1 = __expf(d0[1]);
            float e2 = __expf(d0[2]), e3 = __expf(d0[3]);
            float e4 = __expf(d1[0]), e5 = __expf(d1[1]);
            float e6 = __expf(d1[2]), e7 = __expf(d1[3]);
            uint32_t afr[4];
            asm("cvt.rn.bf16x2.f32 %0, %1, %2;" : "=r"(afr[0]) : "f"(e1), "f"(e0));
            asm("cvt.rn.bf16x2.f32 %0, %1, %2;" : "=r"(afr[1]) : "f"(e3), "f"(e2));
            asm("cvt.rn.bf16x2.f32 %0, %1, %2;" : "=r"(afr[2]) : "f"(e5), "f"(e4));
            asm("cvt.rn.bf16x2.f32 %0, %1, %2;" : "=r"(afr[3]) : "f"(e7), "f"(e6));

            const uint32_t bb = (uint32_t)(k * 32 + qid * 4);
            #pragma unroll
            for (int cc = 0; cc < 8; cc++) {
                const uint32_t cr = (uint32_t)(cc * 8 + grp) * 128;
                uint32_t v0 = *(const uint32_t*)(&vs[buf][0] + SW128(cr + bb));
                uint32_t v1 = *(const uint32_t*)(&vs[buf][0] + SW128(cr + bb + 16));
                mma16816(acc[cc], afr, v0, v1);
            }
        }
        __syncthreads();   // staging of ch+1 complete; reads of buf done
    }

    // Epilogue: D fragment -> out = D*scale + x (layout unchanged from R15)
    const float scale = (a == 0) ? beta[0] : gamma[0];
    const float* xin  = (a == 0) ? x2 : x1;
    float* ob = out + (a == 0 ? (size_t)NB * NC * NN : 0);
    const int jlo = j0 + jr;
    #pragma unroll
    for (int cc = 0; cc < 8; cc++) {
        const int c0 = cc * 8 + qid * 2;
        size_t g00 = ((size_t)b * NC + c0) * NN + jlo;
        ob[g00]          = acc[cc][0] * scale + xin[g00];
        ob[g00 + NN]     = acc[cc][1] * scale + xin[g00 + NN];
        ob[g00 + 8]      = acc[cc][2] * scale + xin[g00 + 8];
        ob[g00 + NN + 8] = acc[cc][3] * scale + xin[g00 + NN + 8];
    }
}

// ---------------------------------------------------------------------------
extern "C" void kernel_launch(void* const* d_in, const int* in_sizes, int n_in,
                              void* d_out, int out_size)
{
    (void)in_sizes; (void)n_in; (void)out_size;
    const float* x1   = (const float*)d_in[0];
    const float* x2   = (const float*)d_in[1];
    const float* Wqk1 = (const float*)d_in[2];
    const float* bqk1 = (const float*)d_in[3];
    const float* Wqk2 = (const float*)d_in[4];
    const float* bqk2 = (const float*)d_in[5];
    const float* Wv1  = (const float*)d_in[6];
    const float* bv1  = (const float*)d_in[7];
    const float* Wv2  = (const float*)d_in[8];
    const float* bv2  = (const float*)d_in[9];
    const float* gamma = (const float*)d_in[10];
    const float* beta  = (const float*)d_in[11];
    float* out = (float*)d_out;

    const int proj_smem  = 26784 * sizeof(float);          // 107136 B
    const int stats_smem = (8 * NN + 128) * sizeof(float); // 74240 B
    cudaFuncSetAttribute(k_proj,  cudaFuncAttributeMaxDynamicSharedMemorySize, proj_smem);
    cudaFuncSetAttribute(k_stats, cudaFuncAttributeMaxDynamicSharedMemorySize, stats_smem);

    k_proj<<<dim3(NN / 128, NB), 512, proj_smem>>>(x1, x2, Wqk1, bqk1, Wqk2, bqk2,
                                                   Wv1, bv1, Wv2, bv2);
    k_stats<<<dim3(NN / 128, 2, NB), 256, stats_smem>>>();
    k_apply<<<dim3(NN / JT, 2, NB), 256>>>(x1, x2, gamma, beta, out);
}